// round 1
// baseline (speedup 1.0000x reference)
#include <cuda_runtime.h>
#include <cuda_bf16.h>

// Conv2d 3x3, stride 1, pad 1, NCHW.
// x: [32, 64, 112, 112] f32
// w: [128, 64, 3, 3]    f32
// b: [128]              f32
// out: [32, 128, 112, 112] f32
//
// Block: 256 threads -> 64 out-channels x 16x16 pixel tile of one image.
// Thread: 8 channels x 8 pixels (8x8 register tile).
// Input channels processed in chunks of CI=8 staged through shared memory.

#define CONV_N   32
#define CONV_C   64
#define CONV_K   128
#define CONV_HW  112
#define CI       8          // input-channel chunk
#define TILE     16         // output spatial tile (16x16)
#define HALO     18         // TILE + 2
#define KB       64         // output channels per block

__global__ __launch_bounds__(256, 2)
void conv3x3_kernel(const float* __restrict__ x,
                    const float* __restrict__ w,
                    const float* __restrict__ b,
                    float* __restrict__ out)
{
    __shared__ float sX[CI * HALO * HALO];   // 8*18*18 = 2592 floats
    __shared__ float sW[KB * CI * 9];        // 64*72  = 4608 floats

    const int tid  = threadIdx.x;
    const int tile = blockIdx.x;           // 0..48
    const int th   = tile / 7;
    const int tw   = tile - th * 7;
    const int kg   = blockIdx.y;           // 0..1 (output channel group)
    const int n    = blockIdx.z;           // 0..31

    const int tcol = tid & 31;             // pixel-column group
    const int trow = tid >> 5;             // channel group (0..7)
    const int t16  = tcol >> 4;            // 0/1: which row pair
    const int px   = tcol & 15;            // column within tile

    const int oy0 = th * TILE;
    const int ox0 = tw * TILE;

    // accumulators: 8 channels x 8 pixels
    float acc[8][8];
#pragma unroll
    for (int i = 0; i < 8; i++) {
        const float bv = b[kg * KB + trow * 8 + i];
#pragma unroll
        for (int j = 0; j < 8; j++) acc[i][j] = bv;
    }

    // base offset into sX for this thread's pixel set (per channel c add c*324)
    const int xb = t16 * HALO + px;

    for (int cb = 0; cb < CONV_C; cb += CI) {
        // ---- stage input tile (with halo, zero-padded) ----
        for (int idx = tid; idx < CI * HALO * HALO; idx += 256) {
            const int c   = idx / (HALO * HALO);
            const int rem = idx - c * (HALO * HALO);
            const int r   = rem / HALO;
            const int cc  = rem - r * HALO;
            const int gy  = oy0 - 1 + r;
            const int gx  = ox0 - 1 + cc;
            float v = 0.0f;
            if ((unsigned)gy < (unsigned)CONV_HW && (unsigned)gx < (unsigned)CONV_HW)
                v = x[((n * CONV_C + cb + c) * CONV_HW + gy) * CONV_HW + gx];
            sX[idx] = v;
        }
        // ---- stage weights: sW[k*72 + c*9 + tap] (k-row contiguous) ----
        for (int idx = tid; idx < KB * CI * 9; idx += 256) {
            const int k   = idx / (CI * 9);
            const int rem = idx - k * (CI * 9);        // c*9 + tap
            sW[idx] = w[(kg * KB + k) * (CONV_C * 9) + cb * 9 + rem];
        }
        __syncthreads();

        // ---- compute: per (c, dy, dx): 8 x-loads + 8 w-loads -> 64 FMA ----
#pragma unroll
        for (int c = 0; c < CI; c++) {
#pragma unroll
            for (int dy = 0; dy < 3; dy++) {
#pragma unroll
                for (int dx = 0; dx < 3; dx++) {
                    float xr[8];
                    const int base = c * (HALO * HALO) + xb + dy * HALO + dx;
#pragma unroll
                    for (int j = 0; j < 8; j++)
                        xr[j] = sX[base + 36 * j];     // pixels 2 rows apart
#pragma unroll
                    for (int i = 0; i < 8; i++) {
                        const float wv = sW[(trow * 8 + i) * (CI * 9) + c * 9 + dy * 3 + dx];
#pragma unroll
                        for (int j = 0; j < 8; j++)
                            acc[i][j] = fmaf(wv, xr[j], acc[i][j]);
                    }
                }
            }
        }
        __syncthreads();
    }

    // ---- write out ----
#pragma unroll
    for (int i = 0; i < 8; i++) {
        const int k = kg * KB + trow * 8 + i;
        float* orow = out + ((size_t)(n * CONV_K + k) * CONV_HW) * CONV_HW;
#pragma unroll
        for (int j = 0; j < 8; j++) {
            const int py = 2 * j + t16;
            orow[(size_t)(oy0 + py) * CONV_HW + ox0 + px] = acc[i][j];
        }
    }
}

extern "C" void kernel_launch(void* const* d_in, const int* in_sizes, int n_in,
                              void* d_out, int out_size)
{
    const float* x = (const float*)d_in[0];
    const float* w = (const float*)d_in[1];
    const float* b = (const float*)d_in[2];
    float* out = (float*)d_out;

    dim3 grid(49, 2, 32);   // 7x7 spatial tiles, 2 channel groups, 32 images
    dim3 block(256);
    conv3x3_kernel<<<grid, block>>>(x, w, b, out);
}

// round 2
// speedup vs baseline: 1.2645x; 1.2645x over previous
#include <cuda_runtime.h>
#include <cuda_bf16.h>

// Conv2d 3x3, stride 1, pad 1, NCHW — f32x2 packed-FMA version.
// x: [32, 64, 112, 112] f32
// w: [128, 64, 3, 3]    f32
// b: [128]              f32
// out: [32, 128, 112, 112] f32
//
// Block: 256 threads -> 64 out-channels x 16x16 pixel tile of one image.
// Thread: 8 out-channels x (2 cols x 4 rows) = 8 x 4 f32x2 accumulators.
// Input channels in chunks of CI=8 staged in smem; weights duplicated {w,w}
// in smem so the FFMA2 b-operand is a single broadcast LDS.64.

#define CONV_N   32
#define CONV_C   64
#define CONV_K   128
#define CONV_HW  112
#define CI       8
#define TILE     16
#define HALO     18          // logical halo rows/cols
#define XPITCH   20          // padded row pitch (floats) -> conflict-free LDS.64
#define XCH      (HALO * XPITCH)   // 360 floats per input channel
#define KB       64

typedef unsigned long long ull;

__device__ __forceinline__ void ffma2(ull& d, ull a, ull b) {
    asm volatile("fma.rn.f32x2 %0, %1, %2, %0;" : "+l"(d) : "l"(a), "l"(b));
}
__device__ __forceinline__ ull pk(float lo, float hi) {
    ull r;
    asm("mov.b64 %0, {%1, %2};" : "=l"(r) : "f"(lo), "f"(hi));
    return r;
}
__device__ __forceinline__ float2 unpk(ull v) {
    float2 r;
    asm("mov.b64 {%0, %1}, %2;" : "=f"(r.x), "=f"(r.y) : "l"(v));
    return r;
}

__global__ __launch_bounds__(256, 2)
void conv3x3_f32x2_kernel(const float* __restrict__ x,
                          const float* __restrict__ w,
                          const float* __restrict__ b,
                          float* __restrict__ out)
{
    __shared__ float sX[CI * XCH];          // 2880 floats = 11.25 KB
    __shared__ float sWd[KB * CI * 9 * 2];  // 9216 floats = 36 KB (dup pairs)

    const int tid  = threadIdx.x;
    const int tile = blockIdx.x;            // 0..48
    const int th   = tile / 7;
    const int tw   = tile - th * 7;
    const int kg   = blockIdx.y;            // 0..1
    const int n    = blockIdx.z;            // 0..31

    const int tcol = tid & 31;
    const int trow = tid >> 5;              // out-channel octet 0..7
    const int rg   = tcol >> 3;             // row group 0..3 (4 rows each)
    const int q    = tcol & 7;              // column pair 0..7

    const int oy0 = th * TILE;
    const int ox0 = tw * TILE;

    // accumulators: 8 channels x 4 row-pairs (lo=col 2q, hi=col 2q+1)
    ull acc[8][4];
#pragma unroll
    for (int i = 0; i < 8; i++) {
        const float bv = b[kg * KB + trow * 8 + i];
        const ull bp = pk(bv, bv);
#pragma unroll
        for (int jr = 0; jr < 4; jr++) acc[i][jr] = bp;
    }

    for (int cb = 0; cb < CONV_C; cb += CI) {
        // ---- stage input tile (halo, zero-padded), pitch 20 ----
        for (int idx = tid; idx < CI * HALO * HALO; idx += 256) {
            const int c   = idx / (HALO * HALO);
            const int rem = idx - c * (HALO * HALO);
            const int r   = rem / HALO;
            const int cc  = rem - r * HALO;
            const int gy  = oy0 - 1 + r;
            const int gx  = ox0 - 1 + cc;
            float v = 0.0f;
            if ((unsigned)gy < (unsigned)CONV_HW && (unsigned)gx < (unsigned)CONV_HW)
                v = x[((n * CONV_C + cb + c) * CONV_HW + gy) * CONV_HW + gx];
            sX[c * XCH + r * XPITCH + cc] = v;
        }
        // ---- stage weights duplicated: sWd[2*(k*72 + c*9 + tap)] = {w,w} ----
        for (int idx = tid; idx < KB * CI * 9; idx += 256) {
            const int k   = idx / (CI * 9);
            const int rem = idx - k * (CI * 9);
            const float v = w[(kg * KB + k) * (CONV_C * 9) + cb * 9 + rem];
            *(float2*)&sWd[2 * idx] = make_float2(v, v);
        }
        __syncthreads();

        // ---- compute ----
#pragma unroll
        for (int c = 0; c < CI; c++) {
#pragma unroll
            for (int dy = 0; dy < 3; dy++) {
#pragma unroll
                for (int dx = 0; dx < 3; dx++) {
                    // 8 duplicated weight pairs (broadcast LDS.64)
                    ull wp[8];
#pragma unroll
                    for (int i = 0; i < 8; i++)
                        wp[i] = *(const ull*)&sWd[2 * ((trow * 8 + i) * (CI * 9) + c * 9 + dy * 3 + dx)];
#pragma unroll
                    for (int jr = 0; jr < 4; jr++) {
                        const int rr  = rg * 4 + jr + dy;
                        const int off = c * XCH + rr * XPITCH + 2 * q + dx;
                        ull xp;
                        if (dx == 1) {
                            xp = pk(sX[off], sX[off + 1]);   // odd offset: 2x LDS.32
                        } else {
                            xp = *(const ull*)&sX[off];       // even offset: LDS.64
                        }
#pragma unroll
                        for (int i = 0; i < 8; i++)
                            ffma2(acc[i][jr], xp, wp[i]);
                    }
                }
            }
        }
        __syncthreads();
    }

    // ---- write out (float2 stores, 8B aligned) ----
#pragma unroll
    for (int i = 0; i < 8; i++) {
        const int k = kg * KB + trow * 8 + i;
        float* obase = out + (size_t)(n * CONV_K + k) * (CONV_HW * CONV_HW);
#pragma unroll
        for (int jr = 0; jr < 4; jr++) {
            const int row = oy0 + rg * 4 + jr;
            *(float2*)&obase[(size_t)row * CONV_HW + ox0 + 2 * q] = unpk(acc[i][jr]);
        }
    }
}

extern "C" void kernel_launch(void* const* d_in, const int* in_sizes, int n_in,
                              void* d_out, int out_size)
{
    const float* x = (const float*)d_in[0];
    const float* w = (const float*)d_in[1];
    const float* b = (const float*)d_in[2];
    float* out = (float*)d_out;

    dim3 grid(49, 2, 32);
    dim3 block(256);
    conv3x3_f32x2_kernel<<<grid, block>>>(x, w, b, out);
}

// round 5
// speedup vs baseline: 2.3434x; 1.8533x over previous
#include <cuda_runtime.h>
#include <cuda_bf16.h>
#include <cstdint>

// Conv2d 3x3 s1 p1 NCHW as implicit GEMM via mma.sync tf32 (baseline PTX, sm_80+).
// x: [32,64,112,112] f32   w: [128,64,3,3]=[128][576] f32   b:[128]
// out: [32,128,112,112] f32
//
// CTA: 128 ko x 256 px (16x16 tile, one image). 8 warps, warp tile 64x64.
// K=576 in 18 chunks of 32, double-buffered smem, m16n8k8 tf32 atoms.

#define HW    112
#define IMG   (HW * HW)
#define CIN   64
#define KOUT  128
#define KTOT  576
#define KC    32
#define NCH   18
#define PA    136              // sA pitch (uint32 elems): 128 + 8 pad
#define PB    264              // sB pitch: 256 + 8 pad
#define BUFU  (KC * (PA + PB)) // uint32s per buffer = 12800
#define SMEM_TOTAL (2 * BUFU * 4)  // 102400 B

__device__ __forceinline__ uint32_t cvt_tf32(float x) {
    uint32_t r;
    asm("cvt.rna.tf32.f32 %0, %1;" : "=r"(r) : "f"(x));
    return r;
}

__device__ __forceinline__ void mma8(float* d, const uint32_t* a, const uint32_t* b) {
    asm volatile(
        "mma.sync.aligned.m16n8k8.row.col.f32.tf32.tf32.f32 "
        "{%0,%1,%2,%3}, {%4,%5,%6,%7}, {%8,%9}, {%0,%1,%2,%3};"
        : "+f"(d[0]), "+f"(d[1]), "+f"(d[2]), "+f"(d[3])
        : "r"(a[0]), "r"(a[1]), "r"(a[2]), "r"(a[3]), "r"(b[0]), "r"(b[1]));
}

__global__ __launch_bounds__(256, 1)
void conv_mma_tf32(const float* __restrict__ x,
                   const float* __restrict__ w,
                   const float* __restrict__ bias,
                   float* __restrict__ out)
{
    extern __shared__ uint32_t smem[];

    const int tid  = threadIdx.x;
    const int warp = tid >> 5;
    const int lane = tid & 31;
    const int g    = lane >> 2;          // groupID 0..7
    const int tig  = lane & 3;           // thread-in-group 0..3

    const int warp_m = warp >> 2;        // 0..1
    const int warp_n = warp & 3;         // 0..3
    const int ko_w = warp_m * 64;
    const int px_w = warp_n * 64;

    const int tile = blockIdx.x;         // 0..48
    const int n    = blockIdx.y;         // 0..31
    const int py0  = (tile / 7) * 16;
    const int px0  = (tile % 7) * 16;

    // B-gather coords: row p = tid (p = y*16 + x within tile)
    const int ty  = tid >> 4;
    const int tx  = tid & 15;
    const int gy0 = py0 + ty - 1;
    const int gx0 = px0 + tx - 1;
    const float* xn = x + (size_t)n * CIN * IMG;

    float acc[4][8][4];
#pragma unroll
    for (int mi = 0; mi < 4; mi++)
#pragma unroll
        for (int ni = 0; ni < 8; ni++)
#pragma unroll
            for (int r = 0; r < 4; r++) acc[mi][ni][r] = 0.0f;

    // ---- staging ----
    auto stage = [&](int s, int buf) {
        uint32_t* sA = smem + buf * BUFU;
        uint32_t* sB = sA + KC * PA;
        const int k0 = s * KC;
        // A: w[ko][k0..k0+31] -> sA[kk][ko]
#pragma unroll
        for (int v = tid; v < KOUT * KC; v += 256) {
            const int ko = v >> 5;
            const int kk = v & 31;
            sA[kk * PA + ko] = cvt_tf32(__ldg(w + ko * KTOT + k0 + kk));
        }
        // B: im2col gather, thread = px row
#pragma unroll
        for (int k = 0; k < KC; k++) {
            const int kg  = k0 + k;
            const int c   = kg / 9;
            const int tap = kg - c * 9;
            const int dy  = tap / 3;
            const int dx  = tap - dy * 3;
            const int gy  = gy0 + dy;
            const int gx  = gx0 + dx;
            float v = 0.0f;
            if ((unsigned)gy < (unsigned)HW && (unsigned)gx < (unsigned)HW)
                v = __ldg(xn + c * IMG + gy * HW + gx);
            sB[k * PB + tid] = cvt_tf32(v);
        }
    };

    // ---- compute one 32-K chunk ----
    auto compute = [&](int buf) {
        const uint32_t* sA = smem + buf * BUFU;
        const uint32_t* sB = sA + KC * PA;
#pragma unroll
        for (int ks = 0; ks < 4; ks++) {
            uint32_t af[4][4], bf[8][2];
            const uint32_t* aK0 = sA + (ks * 8 + tig) * PA + ko_w + g;
            const uint32_t* aK4 = aK0 + 4 * PA;
#pragma unroll
            for (int mi = 0; mi < 4; mi++) {
                af[mi][0] = aK0[mi * 16];
                af[mi][1] = aK0[mi * 16 + 8];
                af[mi][2] = aK4[mi * 16];
                af[mi][3] = aK4[mi * 16 + 8];
            }
            const uint32_t* bK0 = sB + (ks * 8 + tig) * PB + px_w + g;
            const uint32_t* bK4 = bK0 + 4 * PB;
#pragma unroll
            for (int ni = 0; ni < 8; ni++) {
                bf[ni][0] = bK0[ni * 8];
                bf[ni][1] = bK4[ni * 8];
            }
#pragma unroll
            for (int mi = 0; mi < 4; mi++)
#pragma unroll
                for (int ni = 0; ni < 8; ni++)
                    mma8(acc[mi][ni], af[mi], bf[ni]);
        }
    };

    // ---- pipeline ----
    stage(0, 0);
    __syncthreads();
#pragma unroll 1
    for (int s = 0; s < NCH; s++) {
        if (s + 1 < NCH) stage(s + 1, (s + 1) & 1);
        compute(s & 1);
        __syncthreads();
    }

    // ---- epilogue: bias + store (float2) ----
#pragma unroll
    for (int mi = 0; mi < 4; mi++) {
        const int ko0 = ko_w + mi * 16 + g;
        const float bv0 = __ldg(bias + ko0);
        const float bv1 = __ldg(bias + ko0 + 8);
        float* o0 = out + ((size_t)n * KOUT + ko0) * IMG;
        float* o1 = o0 + 8 * IMG;
#pragma unroll
        for (int ni = 0; ni < 8; ni++) {
            const int p  = px_w + ni * 8 + 2 * tig;
            const int oy = py0 + (p >> 4);
            const int ox = px0 + (p & 15);
            const size_t off = (size_t)oy * HW + ox;
            float2 v0 = make_float2(acc[mi][ni][0] + bv0, acc[mi][ni][1] + bv0);
            float2 v1 = make_float2(acc[mi][ni][2] + bv1, acc[mi][ni][3] + bv1);
            *(float2*)(o0 + off) = v0;
            *(float2*)(o1 + off) = v1;
        }
    }
}

extern "C" void kernel_launch(void* const* d_in, const int* in_sizes, int n_in,
                              void* d_out, int out_size)
{
    const float* x = (const float*)d_in[0];
    const float* w = (const float*)d_in[1];
    const float* b = (const float*)d_in[2];
    float* out = (float*)d_out;

    cudaFuncSetAttribute(conv_mma_tf32,
                         cudaFuncAttributeMaxDynamicSharedMemorySize, SMEM_TOTAL);

    dim3 grid(49, 32);
    dim3 block(256);
    conv_mma_tf32<<<grid, block, SMEM_TOTAL>>>(x, w, b, out);
}

// round 6
// speedup vs baseline: 2.6911x; 1.1483x over previous
#include <cuda_runtime.h>
#include <cuda_bf16.h>
#include <cstdint>

// Conv2d 3x3 s1 p1 NCHW as implicit GEMM via mma.sync tf32, cp.async multistage.
// x: [32,64,112,112] f32   w: [128,64,3,3]=[128][576] f32   b:[128]
// out: [32,128,112,112] f32
//
// CTA: 128 ko x 256 px (16x16 tile, one image). 8 warps, warp tile 64x64.
// K=576 in 18 chunks of 32. 4 smem buffers, 3 staging groups in flight.
// A: LDG prefetch -> cvt.rna.tf32 -> STS.128 (pre-converted, paired rows).
// B: cp.async 4B zfill gather (raw f32, cvt at fragment load), paired k's.

#define HW    112
#define IMG   (HW * HW)
#define KTOT  576
#define KOUT  128
#define KC    32
#define NCH   18
#define NBUF  4

#define PAP   68                    // float2 per A k-row: 64 pairs + 4 pad  (68%16==4)
#define PBP   260                   // float2 per B kp-row: 256 + 4 pad      (260%16==4)
#define A_F2  (KC * PAP)            // 2176
#define B_F2  (16 * PBP)            // 4160
#define A_BYTES   (A_F2 * 8)        // 17408
#define BUF_BYTES ((A_F2 + B_F2) * 8)   // 50688
#define SMEM_TOTAL (NBUF * BUF_BYTES)   // 202752

__device__ __forceinline__ uint32_t cvt_tf32(float x) {
    uint32_t r;
    asm("cvt.rna.tf32.f32 %0, %1;" : "=r"(r) : "f"(x));
    return r;
}
__device__ __forceinline__ uint32_t smem_u32(const void* p) {
    uint32_t a;
    asm("{ .reg .u64 t; cvta.to.shared.u64 t, %1; cvt.u32.u64 %0, t; }" : "=r"(a) : "l"(p));
    return a;
}
__device__ __forceinline__ uint2 lds_u2(uint32_t a) {
    uint2 v;
    asm volatile("ld.shared.v2.b32 {%0,%1}, [%2];" : "=r"(v.x), "=r"(v.y) : "r"(a));
    return v;
}
__device__ __forceinline__ float2 lds_f2(uint32_t a) {
    float2 v;
    asm volatile("ld.shared.v2.f32 {%0,%1}, [%2];" : "=f"(v.x), "=f"(v.y) : "r"(a));
    return v;
}
__device__ __forceinline__ void sts128(uint32_t a, uint32_t v0, uint32_t v1,
                                       uint32_t v2, uint32_t v3) {
    asm volatile("st.shared.v4.b32 [%0], {%1,%2,%3,%4};"
                 :: "r"(a), "r"(v0), "r"(v1), "r"(v2), "r"(v3));
}
__device__ __forceinline__ void cpa4(uint32_t dst, const float* src, int sz) {
    asm volatile("cp.async.ca.shared.global [%0], [%1], 4, %2;"
                 :: "r"(dst), "l"(src), "r"(sz));
}
__device__ __forceinline__ void cpa_commit() {
    asm volatile("cp.async.commit_group;" ::: "memory");
}
__device__ __forceinline__ void mma8(float* d, const uint32_t* a, const uint32_t* b) {
    asm volatile(
        "mma.sync.aligned.m16n8k8.row.col.f32.tf32.tf32.f32 "
        "{%0,%1,%2,%3}, {%4,%5,%6,%7}, {%8,%9}, {%0,%1,%2,%3};"
        : "+f"(d[0]), "+f"(d[1]), "+f"(d[2]), "+f"(d[3])
        : "r"(a[0]), "r"(a[1]), "r"(a[2]), "r"(a[3]), "r"(b[0]), "r"(b[1]));
}

__global__ __launch_bounds__(256, 1)
void conv_mma_async(const float* __restrict__ x,
                    const float* __restrict__ w,
                    const float* __restrict__ bias,
                    float* __restrict__ out)
{
    extern __shared__ __align__(16) char dsm[];
    const uint32_t sb = smem_u32(dsm);

    const int tid  = threadIdx.x;
    const int warp = tid >> 5;
    const int lane = tid & 31;
    const int g    = lane >> 2;
    const int tig  = lane & 3;
    const int warp_m = warp >> 2;        // 0..1
    const int warp_n = warp & 3;         // 0..3

    const int tile = blockIdx.x;         // 0..48
    const int n    = blockIdx.y;         // 0..31
    const int py0  = (tile / 7) * 16;
    const int px0  = (tile % 7) * 16;

    // B-gather coords: row px = tid
    const int ty  = tid >> 4;
    const int tx  = tid & 15;
    const int gy0 = py0 + ty - 1;
    const int gx0 = px0 + tx - 1;
    const float* xn = x + (size_t)n * 64 * IMG;

    float acc[4][8][4];
#pragma unroll
    for (int mi = 0; mi < 4; mi++)
#pragma unroll
        for (int ni = 0; ni < 8; ni++)
#pragma unroll
            for (int r = 0; r < 4; r++) acc[mi][ni][r] = 0.0f;

    // ---- A staging: LDG 16 scalars (coalesced rows of w) -> cvt -> 4x STS.128 ----
    auto ldA = [&](int s, float ap[4][4]) {
        const int k0 = s * KC;
#pragma unroll
        for (int i = 0; i < 4; i++) {
            const int pq = warp + i * 8;              // pair-quad index 0..31
            const int b  = pq >> 2;
            const int gg = (pq & 3) * 2;
            const float* wp = w + (b * 16 + gg) * KTOT + k0 + lane;
            ap[i][0] = __ldg(wp);                     // row b*16+gg,   slot h=0 of pair 2pq
            ap[i][1] = __ldg(wp + 8 * KTOT);          // row b*16+gg+8, slot h=1 of pair 2pq
            ap[i][2] = __ldg(wp + 1 * KTOT);          // pair 2pq+1, h=0
            ap[i][3] = __ldg(wp + 9 * KTOT);          // pair 2pq+1, h=1
        }
    };
    auto stA = [&](uint32_t abase, float ap[4][4]) {
#pragma unroll
        for (int i = 0; i < 4; i++) {
            const int pq = warp + i * 8;
            sts128(abase + (uint32_t)(lane * 34 + pq) * 16,
                   cvt_tf32(ap[i][0]), cvt_tf32(ap[i][1]),
                   cvt_tf32(ap[i][2]), cvt_tf32(ap[i][3]));
        }
    };
    // ---- B staging: 32 cp.async 4B gathers per thread (zero-fill OOB) ----
    auto stB = [&](int s, uint32_t bbase) {
        const int k0 = s * KC;
#pragma unroll
        for (int k = 0; k < KC; k++) {
            const int kg  = k0 + k;
            const int c   = kg / 9;
            const int tap = kg - c * 9;
            const int dy  = tap / 3;
            const int dx  = tap - dy * 3;
            const int gy  = gy0 + dy;
            const int gx  = gx0 + dx;
            const bool p  = ((unsigned)gy < (unsigned)HW) & ((unsigned)gx < (unsigned)HW);
            const float* src = p ? (xn + c * IMG + gy * HW + gx) : xn;
            const int kp = (k >> 3) * 4 + (k & 3);
            const int h  = (k >> 2) & 1;
            cpa4(bbase + (uint32_t)(kp * 520 + tid * 2 + h) * 4, src, p ? 4 : 0);
        }
    };

    // ---- compute one chunk from buffer buf ----
    auto compute = [&](int buf) {
        const uint32_t ab = sb + (uint32_t)buf * BUF_BYTES;
        const uint32_t bb = ab + A_BYTES;
#pragma unroll
        for (int ks = 0; ks < 4; ks++) {
            uint32_t af[4][4], bf[8][2];
            const uint32_t a0 = ab + (uint32_t)((ks * 8 + tig) * PAP + warp_m * 32 + g) * 8;
#pragma unroll
            for (int mi = 0; mi < 4; mi++) {
                uint2 p0 = lds_u2(a0 + mi * 64);                 // k = ks*8+tig
                uint2 p1 = lds_u2(a0 + 4 * PAP * 8 + mi * 64);   // k = ks*8+tig+4
                af[mi][0] = p0.x; af[mi][1] = p0.y;
                af[mi][2] = p1.x; af[mi][3] = p1.y;
            }
            const uint32_t b0 = bb + (uint32_t)((ks * 4 + tig) * PBP + warp_n * 64 + g) * 8;
#pragma unroll
            for (int ni = 0; ni < 8; ni++) {
                float2 pb = lds_f2(b0 + ni * 64);
                bf[ni][0] = cvt_tf32(pb.x);
                bf[ni][1] = cvt_tf32(pb.y);
            }
#pragma unroll
            for (int mi = 0; mi < 4; mi++)
#pragma unroll
                for (int ni = 0; ni < 8; ni++)
                    mma8(acc[mi][ni], af[mi], bf[ni]);
        }
    };

    // ---- prologue: stage chunks 0..2 into buffers 0..2 ----
#pragma unroll 1
    for (int p = 0; p < 3; p++) {
        float ap[4][4];
        ldA(p, ap);
        stA(sb + (uint32_t)p * BUF_BYTES, ap);
        stB(p, sb + (uint32_t)p * BUF_BYTES + A_BYTES);
        cpa_commit();
    }

    // ---- mainloop ----
#pragma unroll 1
    for (int s = 0; s < NCH; s++) {
        float ap[4][4];
        const bool do_stage = (s + 3 < NCH);
        if (do_stage) ldA(s + 3, ap);                 // LDG early: latency hidden by wait

        if (s < 16)       asm volatile("cp.async.wait_group 2;" ::: "memory");
        else if (s == 16) asm volatile("cp.async.wait_group 1;" ::: "memory");
        else              asm volatile("cp.async.wait_group 0;" ::: "memory");
        __syncthreads();

        if (do_stage) {
            const int buf = (s + 3) & 3;
            stA(sb + (uint32_t)buf * BUF_BYTES, ap);
            stB(s + 3, sb + (uint32_t)buf * BUF_BYTES + A_BYTES);
            cpa_commit();
        }
        compute(s & 3);
    }

    // ---- epilogue: bias + float2 stores ----
#pragma unroll
    for (int mi = 0; mi < 4; mi++) {
        const int ko0 = warp_m * 64 + mi * 16 + g;
        const float bv0 = __ldg(bias + ko0);
        const float bv1 = __ldg(bias + ko0 + 8);
        float* o0 = out + ((size_t)n * KOUT + ko0) * IMG;
        float* o1 = o0 + 8 * IMG;
#pragma unroll
        for (int ni = 0; ni < 8; ni++) {
            const int p  = warp_n * 64 + ni * 8 + 2 * tig;
            const int oy = py0 + (p >> 4);
            const int ox = px0 + (p & 15);
            const size_t off = (size_t)oy * HW + ox;
            *(float2*)(o0 + off) = make_float2(acc[mi][ni][0] + bv0, acc[mi][ni][1] + bv0);
            *(float2*)(o1 + off) = make_float2(acc[mi][ni][2] + bv1, acc[mi][ni][3] + bv1);
        }
    }
}

extern "C" void kernel_launch(void* const* d_in, const int* in_sizes, int n_in,
                              void* d_out, int out_size)
{
    const float* x = (const float*)d_in[0];
    const float* w = (const float*)d_in[1];
    const float* b = (const float*)d_in[2];
    float* out = (float*)d_out;

    cudaFuncSetAttribute(conv_mma_async,
                         cudaFuncAttributeMaxDynamicSharedMemorySize, SMEM_TOTAL);

    dim3 grid(49, 32);
    dim3 block(256);
    conv_mma_async<<<grid, block, SMEM_TOTAL>>>(x, w, b, out);
}

// round 8
// speedup vs baseline: 4.2484x; 1.5787x over previous
#include <cuda_runtime.h>
#include <cuda_bf16.h>
#include <cstdint>

// Conv2d 3x3 s1 p1 NCHW, implicit GEMM, mma.sync tf32, halo-tile B assembly.
// x: [32,64,112,112] f32   w: [128,64,3,3]=[128][576] f32   b:[128]
// out: [32,128,112,112] f32
//
// CTA: 128 ko x 256 px (16x16 tile, one image). 8 warps, warp tile 64x64.
// K processed as 8 chunks of (8 channels x 9 taps = 72 k). mma k-octets are
// tap-major: octet t has tap=(t/3,t%3) fixed, channel = tig+4h.
// A: raw f32, natural k-order, 16B cp.async; permutation folded into frag col.
// B: raw x halo tile (8ch x 18x18, pitch 20), fragments read directly.

#define HW    112
#define IMG   (HW * HW)
#define KTOT  576
#define KOUT  128

#define PW        100                     // sA pitch (words), 100%32==4
#define A_BYTES   (KOUT * PW * 4)         // 51200
#define H_PITCH   20                      // halo pitch (floats)
#define H_CH      (18 * H_PITCH)          // 360 words/channel, 360%32==8
#define H_BYTES   (8 * H_CH * 4)          // 11520
#define STAGE_B   (A_BYTES + H_BYTES)     // 62720
#define NBUF      3
#define SMEM_TOTAL (NBUF * STAGE_B)       // 188160

__device__ __forceinline__ uint32_t cvt_tf32(float x) {
    uint32_t r;
    asm("cvt.rna.tf32.f32 %0, %1;" : "=r"(r) : "f"(x));
    return r;
}
__device__ __forceinline__ uint32_t smem_u32(const void* p) {
    uint32_t a;
    asm("{ .reg .u64 t; cvta.to.shared.u64 t, %1; cvt.u32.u64 %0, t; }" : "=r"(a) : "l"(p));
    return a;
}
__device__ __forceinline__ float lds_f32(uint32_t a) {
    float v;
    asm volatile("ld.shared.f32 %0, [%1];" : "=f"(v) : "r"(a));
    return v;
}
__device__ __forceinline__ void cpa16(uint32_t dst, const float* src) {
    asm volatile("cp.async.cg.shared.global [%0], [%1], 16;" :: "r"(dst), "l"(src));
}
__device__ __forceinline__ void cpa4(uint32_t dst, const float* src, int sz) {
    asm volatile("cp.async.ca.shared.global [%0], [%1], 4, %2;"
                 :: "r"(dst), "l"(src), "r"(sz));
}
__device__ __forceinline__ void cpa_commit() {
    asm volatile("cp.async.commit_group;" ::: "memory");
}
__device__ __forceinline__ void mma8(float* d, const uint32_t* a, const uint32_t* b) {
    asm volatile(
        "mma.sync.aligned.m16n8k8.row.col.f32.tf32.tf32.f32 "
        "{%0,%1,%2,%3}, {%4,%5,%6,%7}, {%8,%9}, {%0,%1,%2,%3};"
        : "+f"(d[0]), "+f"(d[1]), "+f"(d[2]), "+f"(d[3])
        : "r"(a[0]), "r"(a[1]), "r"(a[2]), "r"(a[3]), "r"(b[0]), "r"(b[1]));
}

__global__ __launch_bounds__(256, 1)
void conv_mma_halo(const float* __restrict__ x,
                   const float* __restrict__ w,
                   const float* __restrict__ bias,
                   float* __restrict__ out)
{
    extern __shared__ __align__(16) char dsm[];
    const uint32_t sb = smem_u32(dsm);

    const int tid  = threadIdx.x;
    const int warp = tid >> 5;
    const int lane = tid & 31;
    const int g    = lane >> 2;
    const int tig  = lane & 3;
    const int warp_m = warp >> 2;        // 0..1
    const int warp_n = warp & 3;         // 0..3

    const int tile = blockIdx.x;         // 0..48
    const int n    = blockIdx.y;         // 0..31
    const int py0  = (tile / 7) * 16;
    const int px0  = (tile % 7) * 16;

    const float* xn = x + (size_t)n * 64 * IMG;

    // ---- per-thread staging tables (divisions at init only) ----
    // A: 9 x 16B loads; q = tid + j*256 over 2304 quads; ko=q/18, qk=q%18
    int      asrc[9];
    uint32_t adst[9];
#pragma unroll
    for (int j = 0; j < 9; j++) {
        const int q  = tid + j * 256;
        const int ko = q / 18;
        const int qk = q - ko * 18;
        asrc[j] = ko * KTOT + qk * 4;
        adst[j] = (uint32_t)(ko * (PW * 4) + qk * 16);
    }
    // Halo: warp = channel-in-chunk, lane covers 324 cells in <=11 steps
    const int hc = tid >> 5;
    const int hs = tid & 31;
    int      hsrc[11];
    uint32_t hdst[11];
    unsigned hmask = 0;
#pragma unroll
    for (int j = 0; j < 11; j++) {
        const int  cell = hs + j * 32;
        const bool inr  = cell < 324;
        const int  r    = cell / 18;
        const int  col  = cell - r * 18;
        const int  gy   = py0 - 1 + r;
        const int  gx   = px0 - 1 + col;
        const bool ok   = inr && ((unsigned)gy < (unsigned)HW) &&
                          ((unsigned)gx < (unsigned)HW);
        hsrc[j] = ok ? (gy * HW + gx) : 0;
        hdst[j] = inr ? (uint32_t)(hc * (H_CH * 4) + r * (H_PITCH * 4) + col * 4)
                      : (uint32_t)(hc * (H_CH * 4) + 18 * 4);   // pad-col scratch
        if (ok) hmask |= 1u << j;
    }

    float acc[4][8][4];
#pragma unroll
    for (int mi = 0; mi < 4; mi++)
#pragma unroll
        for (int ni = 0; ni < 8; ni++)
#pragma unroll
            for (int r = 0; r < 4; r++) acc[mi][ni][r] = 0.0f;

    auto stage = [&](int cc, int buf) {
        const uint32_t ab = sb + (uint32_t)buf * STAGE_B;
        const uint32_t hb = ab + A_BYTES;
        const float* wsrc = w + cc * 72;
#pragma unroll
        for (int j = 0; j < 9; j++) cpa16(ab + adst[j], wsrc + asrc[j]);
        const float* xc = xn + (size_t)(cc * 8 + hc) * IMG;
#pragma unroll
        for (int j = 0; j < 11; j++)
            cpa4(hb + hdst[j], xc + hsrc[j], ((hmask >> j) & 1u) ? 4 : 0);
        cpa_commit();
    };

    // fragment base addresses (bytes)
    const uint32_t aoff0 = (uint32_t)(((warp_m * 64 + g) * PW + tig * 9) * 4);
    const uint32_t boff0 = (uint32_t)((tig * H_CH + warp_n * 4 * H_PITCH + g) * 4);

    auto compute = [&](int buf) {
        const uint32_t ab = sb + (uint32_t)buf * STAGE_B;
        const uint32_t a0 = ab + aoff0;
        const uint32_t b0 = ab + A_BYTES + boff0;
#pragma unroll
        for (int t = 0; t < 9; t++) {
            const int dyt = t / 3, dxt = t - dyt * 3;     // compile-time
            uint32_t af[4][4], bf[8][2];
#pragma unroll
            for (int mi = 0; mi < 4; mi++) {
                const uint32_t am = a0 + (uint32_t)(mi * 16 * PW * 4 + t * 4);
                af[mi][0] = cvt_tf32(lds_f32(am));
                af[mi][1] = cvt_tf32(lds_f32(am + 8 * PW * 4));
                af[mi][2] = cvt_tf32(lds_f32(am + 36 * 4));
                af[mi][3] = cvt_tf32(lds_f32(am + 8 * PW * 4 + 36 * 4));
            }
#pragma unroll
            for (int ni = 0; ni < 8; ni++) {
                const uint32_t bm = b0 +
                    (uint32_t)((((ni >> 1) + dyt) * H_PITCH + (ni & 1) * 8 + dxt) * 4);
                bf[ni][0] = cvt_tf32(lds_f32(bm));
                bf[ni][1] = cvt_tf32(lds_f32(bm + 4 * H_CH * 4));
            }
#pragma unroll
            for (int mi = 0; mi < 4; mi++)
#pragma unroll
                for (int ni = 0; ni < 8; ni++)
                    mma8(acc[mi][ni], af[mi], bf[ni]);
        }
    };

    // ---- pipeline: 3 buffers, 2 stages in flight ----
    stage(0, 0);
    stage(1, 1);
#pragma unroll 1
    for (int cc = 0; cc < 8; cc++) {
        if (cc < 7) asm volatile("cp.async.wait_group 1;" ::: "memory");
        else        asm volatile("cp.async.wait_group 0;" ::: "memory");
        __syncthreads();
        if (cc + 2 < 8) stage(cc + 2, (cc + 2) % 3);
        compute(cc % 3);
    }

    // ---- epilogue: bias + float2 stores ----
#pragma unroll
    for (int mi = 0; mi < 4; mi++) {
        const int ko0 = warp_m * 64 + mi * 16 + g;
        const float bv0 = __ldg(bias + ko0);
        const float bv1 = __ldg(bias + ko0 + 8);
        float* o0 = out + ((size_t)n * KOUT + ko0) * IMG;
        float* o1 = o0 + 8 * IMG;
#pragma unroll
        for (int ni = 0; ni < 8; ni++) {
            const int p  = warp_n * 64 + ni * 8 + 2 * tig;
            const int oy = py0 + (p >> 4);
            const int ox = px0 + (p & 15);
            const size_t off = (size_t)oy * HW + ox;
            *(float2*)(o0 + off) = make_float2(acc[mi][ni][0] + bv0, acc[mi][ni][1] + bv0);
            *(float2*)(o1 + off) = make_float2(acc[mi][ni][2] + bv1, acc[mi][ni][3] + bv1);
        }
    }
}

extern "C" void kernel_launch(void* const* d_in, const int* in_sizes, int n_in,
                              void* d_out, int out_size)
{
    const float* x = (const float*)d_in[0];
    const float* w = (const float*)d_in[1];
    const float* b = (const float*)d_in[2];
    float* out = (float*)d_out;

    cudaFuncSetAttribute(conv_mma_halo,
                         cudaFuncAttributeMaxDynamicSharedMemorySize, SMEM_TOTAL);

    dim3 grid(49, 32);
    dim3 block(256);
    conv_mma_halo<<<grid, block, SMEM_TOTAL>>>(x, w, b, out);
}